// round 16
// baseline (speedup 1.0000x reference)
#include <cuda_runtime.h>
#include <cuda_fp16.h>
#include <cstdint>
#include <cstddef>

#define T_DIM 8192
#define D_DIM 2048
#define F_DIM 8192
#define E_DIM 8
#define C_DIM 2048

#define TILE_M 128
#define TILE_N 128
#define KC     32
#define NSTAGE 3
#define STAGE_BYTES (TILE_M * 64 + TILE_N * 64)   // 16384 (A + B, 64B rows)

// ---------------- device scratch (static: allocation-free) ------------------
__device__ __align__(256) __half g_W1h[(size_t)E_DIM * F_DIM * D_DIM]; // [E][F][D]
__device__ __align__(256) __half g_W2h[(size_t)E_DIM * D_DIM * F_DIM]; // [E][D][F]
__device__ __align__(256) __half g_Ah [(size_t)E_DIM * C_DIM * D_DIM]; // [E][C][D]
__device__ __align__(256) __half g_Hh [(size_t)E_DIM * C_DIM * F_DIM]; // [E][C][F]

// ---------------- helpers ----------------------------------------------------
__device__ __forceinline__ uint32_t smem_u32(const void* p) {
    uint32_t a;
    asm("{ .reg .u64 t; cvta.to.shared.u64 t, %1; cvt.u32.u64 %0, t; }"
        : "=r"(a) : "l"(p));
    return a;
}

// 64B-row swizzle: 16B unit q -> q ^ ((row>>1)&3). Conflict-free for
// ldmatrix (8 rows x 16B) and cp.async stores.
__device__ __forceinline__ uint32_t sw_addr(uint32_t base, int row, int unit) {
    return base + (uint32_t)row * 64u + (uint32_t)((unit ^ ((row >> 1) & 3)) * 16);
}

__device__ __forceinline__ void cp16(uint32_t s, const void* g) {
    asm volatile("cp.async.cg.shared.global [%0], [%1], 16;" :: "r"(s), "l"(g));
}

__device__ __forceinline__ void ldsm4(uint32_t* r, uint32_t addr) {
    asm volatile("ldmatrix.sync.aligned.m8n8.x4.shared.b16 {%0,%1,%2,%3}, [%4];"
                 : "=r"(r[0]), "=r"(r[1]), "=r"(r[2]), "=r"(r[3]) : "r"(addr));
}

__device__ __forceinline__ void mma16816(float* c, const uint32_t* a,
                                         uint32_t b0, uint32_t b1) {
    asm volatile(
        "mma.sync.aligned.m16n8k16.row.col.f32.f16.f16.f32 "
        "{%0,%1,%2,%3}, {%4,%5,%6,%7}, {%8,%9}, {%0,%1,%2,%3};"
        : "+f"(c[0]), "+f"(c[1]), "+f"(c[2]), "+f"(c[3])
        : "r"(a[0]), "r"(a[1]), "r"(a[2]), "r"(a[3]), "r"(b0), "r"(b1));
}

// tanh-form GELU (jax.nn.gelu approximate=True), fp32
__device__ __forceinline__ float gelu_f(float x) {
    float u = 0.7978845608028654f * x * (1.0f + 0.044715f * x * x);
    u = fminf(fmaxf(u, -10.0f), 10.0f);
    float e2 = __expf(2.0f * u);
    float t = __fdividef(e2 - 1.0f, e2 + 1.0f);
    return 0.5f * x * (1.0f + t);
}

// ---------------- GEMM mainloop ---------------------------------------------
// A: [TILE_M, Kh] fp16 K-major, B: [TILE_N, Kh] fp16 K-major (both in gmem).
// acc[mi][ni][4] covers warp tile 64(M) x 32(N).
__device__ __forceinline__ void load_chunk(const __half* A, const __half* B, int Kh,
                                           int kc, uint32_t sbase) {
    const int tid = threadIdx.x;
    const __half* gA = A + (size_t)kc * KC;
    const __half* gB = B + (size_t)kc * KC;
#pragma unroll
    for (int i = 0; i < 2; i++) {             // A: 128 rows x 4 units (512)
        int u = i * 256 + tid;
        int row = u >> 2, q = u & 3;
        cp16(sw_addr(sbase, row, q), gA + (size_t)row * Kh + q * 8);
    }
#pragma unroll
    for (int i = 0; i < 2; i++) {             // B: 128 rows x 4 units
        int u = i * 256 + tid;
        int row = u >> 2, q = u & 3;
        cp16(sw_addr(sbase + TILE_M * 64, row, q), gB + (size_t)row * Kh + q * 8);
    }
}

__device__ __forceinline__ void gemm_tile(const __half* A, const __half* B, int Kh,
                                          uint32_t smem_base, float acc[4][4][4]) {
    const int tid = threadIdx.x;
    const int l = tid & 31, w = tid >> 5;
    const int wm = w & 1, wn = w >> 1;        // 2(M) x 4(N) warps
    const int nk = Kh / KC;

    load_chunk(A, B, Kh, 0, smem_base);
    asm volatile("cp.async.commit_group;" ::: "memory");
    load_chunk(A, B, Kh, 1, smem_base + STAGE_BYTES);
    asm volatile("cp.async.commit_group;" ::: "memory");

    // per-thread ldmatrix row indices (constant across chunks)
    const int rowA = wm * 64 + ((l >> 3) & 1) * 8 + (l & 7); // + mi*16
    const int rowB = wn * 32 + ((l >> 4) & 1) * 8 + (l & 7); // + n2*16
    const int unitA_l = (l >> 4);          // + ks*2
    const int unitB_l = ((l >> 3) & 1);    // + ks*2

    for (int k = 0; k < nk; ++k) {
        asm volatile("cp.async.wait_group 1;" ::: "memory");
        __syncthreads();
        const uint32_t aB = smem_base + (uint32_t)(k % NSTAGE) * STAGE_BYTES;
        const uint32_t bB = aB + TILE_M * 64;
#pragma unroll
        for (int ks = 0; ks < 2; ++ks) {
            uint32_t af[4][4], bf[2][4];
#pragma unroll
            for (int mi = 0; mi < 4; ++mi)
                ldsm4(af[mi], sw_addr(aB, rowA + mi * 16, ks * 2 + unitA_l));
#pragma unroll
            for (int n2 = 0; n2 < 2; ++n2)
                ldsm4(bf[n2], sw_addr(bB, rowB + n2 * 16, ks * 2 + unitB_l));
#pragma unroll
            for (int mi = 0; mi < 4; ++mi)
#pragma unroll
                for (int ni = 0; ni < 4; ++ni)
                    mma16816(acc[mi][ni], af[mi],
                             bf[ni >> 1][(ni & 1) * 2], bf[ni >> 1][(ni & 1) * 2 + 1]);
        }
        __syncthreads();
        if (k + 2 < nk)
            load_chunk(A, B, Kh, k + 2, smem_base + (uint32_t)((k + 2) % NSTAGE) * STAGE_BYTES);
        asm volatile("cp.async.commit_group;" ::: "memory");
    }
}

// ---------------- GEMM1: H = gelu(A @ W1^T + b1) ----------------------------
__global__ void __launch_bounds__(256, 2)
gemm1_kernel(const float* __restrict__ b1) {
    __shared__ char smem[NSTAGE * STAGE_BYTES];
    const int tid = threadIdx.x, l = tid & 31, w = tid >> 5;
    const int wm = w & 1, wn = w >> 1;
    const int nt = blockIdx.x, mt = blockIdx.y, e = blockIdx.z;

    float acc[4][4][4];
#pragma unroll
    for (int i = 0; i < 4; i++)
#pragma unroll
        for (int j = 0; j < 4; j++)
#pragma unroll
            for (int q = 0; q < 4; q++) acc[i][j][q] = 0.f;

    const __half* A = g_Ah  + ((size_t)e * C_DIM + (size_t)mt * TILE_M) * D_DIM;
    const __half* B = g_W1h + (size_t)e * F_DIM * D_DIM + (size_t)nt * TILE_N * D_DIM;
    gemm_tile(A, B, D_DIM, smem_u32(smem), acc);

    const int g = l >> 2, t = l & 3;
    const int col0 = nt * TILE_N + wn * 32;
    const float* bb = b1 + (size_t)e * F_DIM + col0;
#pragma unroll
    for (int mi = 0; mi < 4; ++mi)
#pragma unroll
        for (int h = 0; h < 2; ++h) {
            int row = mt * TILE_M + wm * 64 + mi * 16 + g + h * 8;
            __half2* drow = (__half2*)(g_Hh + ((size_t)e * C_DIM + row) * F_DIM + col0);
#pragma unroll
            for (int ni = 0; ni < 4; ++ni) {
                int c = ni * 8 + 2 * t;
                float v0 = gelu_f(acc[mi][ni][h * 2 + 0] + bb[c]);
                float v1 = gelu_f(acc[mi][ni][h * 2 + 1] + bb[c + 1]);
                drow[c >> 1] = __floats2half2_rn(v0, v1);
            }
        }
}

// ---------------- GEMM2: scatter-add (H @ W2^T + b2) * w --------------------
__global__ void __launch_bounds__(256, 2)
gemm2_kernel(const float* __restrict__ b2, const int* __restrict__ top_idx,
             const float* __restrict__ iw, float* __restrict__ out) {
    __shared__ char smem[NSTAGE * STAGE_BYTES];
    const int tid = threadIdx.x, l = tid & 31, w = tid >> 5;
    const int wm = w & 1, wn = w >> 1;
    const int nt = blockIdx.x, mt = blockIdx.y, e = blockIdx.z;

    float acc[4][4][4];
#pragma unroll
    for (int i = 0; i < 4; i++)
#pragma unroll
        for (int j = 0; j < 4; j++)
#pragma unroll
            for (int q = 0; q < 4; q++) acc[i][j][q] = 0.f;

    const __half* A = g_Hh  + ((size_t)e * C_DIM + (size_t)mt * TILE_M) * F_DIM;
    const __half* B = g_W2h + (size_t)e * D_DIM * F_DIM + (size_t)nt * TILE_N * F_DIM;
    gemm_tile(A, B, F_DIM, smem_u32(smem), acc);

    const int g = l >> 2, t = l & 3;
    const int col0 = nt * TILE_N + wn * 32;
    const float* bb = b2 + (size_t)e * D_DIM + col0;
#pragma unroll
    for (int mi = 0; mi < 4; ++mi)
#pragma unroll
        for (int h = 0; h < 2; ++h) {
            int row = mt * TILE_M + wm * 64 + mi * 16 + g + h * 8;  // c index
            int tok = top_idx[(size_t)row * E_DIM + e];
            float wgt = iw[(size_t)tok * E_DIM + e];
            float* orow = out + (size_t)tok * D_DIM + col0;
#pragma unroll
            for (int ni = 0; ni < 4; ++ni) {
                int c = ni * 8 + 2 * t;
                atomicAdd(&orow[c],     (acc[mi][ni][h * 2 + 0] + bb[c])     * wgt);
                atomicAdd(&orow[c + 1], (acc[mi][ni][h * 2 + 1] + bb[c + 1]) * wgt);
            }
        }
}

// ---------------- prep kernels ----------------------------------------------
// src [E][R][Cc] fp32 -> dst [E][Cc][R] fp16 (transpose last two dims)
__global__ void transpose_f32_to_f16(const float* __restrict__ src,
                                     __half* __restrict__ dst, int R, int Cc) {
    __shared__ float tile[32][33];
    const int e = blockIdx.z;
    const float* s = src + (size_t)e * R * Cc;
    __half* d = dst + (size_t)e * Cc * R;
    const int r0 = blockIdx.y * 32, c0 = blockIdx.x * 32;
    const int tx = threadIdx.x, ty = threadIdx.y;   // (32, 8)
#pragma unroll
    for (int j = 0; j < 32; j += 8)
        tile[ty + j][tx] = s[(size_t)(r0 + ty + j) * Cc + c0 + tx];
    __syncthreads();
#pragma unroll
    for (int j = 0; j < 32; j += 8)
        d[(size_t)(c0 + ty + j) * R + r0 + tx] = __float2half_rn(tile[tx][ty + j]);
}

__global__ void gather_kernel(const float* __restrict__ inputs,
                              const int* __restrict__ top_idx) {
    const int c = blockIdx.x, e = blockIdx.y;
    const int t = top_idx[(size_t)c * E_DIM + e];
    const float2* src = (const float2*)(inputs + (size_t)t * D_DIM);
    __half2* dst = (__half2*)(g_Ah + ((size_t)e * C_DIM + c) * D_DIM);
    for (int i = threadIdx.x; i < D_DIM / 2; i += blockDim.x) {
        float2 v = src[i];
        dst[i] = __floats2half2_rn(v.x, v.y);
    }
}

// ---------------- launch -----------------------------------------------------
extern "C" void kernel_launch(void* const* d_in, const int* in_sizes, int n_in,
                              void* d_out, int out_size) {
    const float* inputs  = (const float*)d_in[0];
    const float* iw      = (const float*)d_in[1];
    const int*   top_idx = (const int*)d_in[2];
    const float* W1      = (const float*)d_in[3];
    const float* b1      = (const float*)d_in[4];
    const float* W2      = (const float*)d_in[5];
    const float* b2      = (const float*)d_in[6];
    float* out = (float*)d_out;

    __half *pW1h, *pW2h;
    cudaGetSymbolAddress((void**)&pW1h, g_W1h);
    cudaGetSymbolAddress((void**)&pW2h, g_W2h);

    cudaMemsetAsync(d_out, 0, (size_t)T_DIM * D_DIM * sizeof(float), 0);

    dim3 tb(32, 8);
    transpose_f32_to_f16<<<dim3(F_DIM / 32, D_DIM / 32, E_DIM), tb>>>(W1, pW1h, D_DIM, F_DIM);
    transpose_f32_to_f16<<<dim3(D_DIM / 32, F_DIM / 32, E_DIM), tb>>>(W2, pW2h, F_DIM, D_DIM);
    gather_kernel<<<dim3(C_DIM, E_DIM), 256>>>(inputs, top_idx);

    gemm1_kernel<<<dim3(F_DIM / TILE_N, C_DIM / TILE_M, E_DIM), 256>>>(b1);
    gemm2_kernel<<<dim3(D_DIM / TILE_N, C_DIM / TILE_M, E_DIM), 256>>>(
        b2, top_idx, iw, out);
}

// round 17
// speedup vs baseline: 1.1925x; 1.1925x over previous
#include <cuda_runtime.h>
#include <cuda_fp16.h>
#include <cstdint>
#include <cstddef>

#define T_DIM 8192
#define D_DIM 2048
#define F_DIM 8192
#define E_DIM 8
#define C_DIM 2048

#define TILE_M 128
#define TILE_N 128
#define KC     64
#define NSTAGE 3
#define STAGE_BYTES (TILE_M * 128 + TILE_N * 128)   // 32768 (A + B, 128B rows)
#define SMEM_TOTAL  (NSTAGE * STAGE_BYTES)          // 98304

// ---------------- device scratch (static: allocation-free) ------------------
__device__ __align__(256) __half g_W1h[(size_t)E_DIM * F_DIM * D_DIM]; // [E][F][D]
__device__ __align__(256) __half g_W2h[(size_t)E_DIM * D_DIM * F_DIM]; // [E][D][F]
__device__ __align__(256) __half g_Ah [(size_t)E_DIM * C_DIM * D_DIM]; // [E][C][D]
__device__ __align__(256) __half g_Hh [(size_t)E_DIM * C_DIM * F_DIM]; // [E][C][F]

// ---------------- helpers ----------------------------------------------------
__device__ __forceinline__ uint32_t smem_u32(const void* p) {
    uint32_t a;
    asm("{ .reg .u64 t; cvta.to.shared.u64 t, %1; cvt.u32.u64 %0, t; }"
        : "=r"(a) : "l"(p));
    return a;
}

// 128B-row swizzle: 16B unit q (0..7) -> q ^ (row & 7). Conflict-free for
// cp.async 16B stores and ldmatrix 8-row reads.
__device__ __forceinline__ uint32_t sw_addr(uint32_t base, int row, int unit) {
    return base + (uint32_t)row * 128u + (uint32_t)((unit ^ (row & 7)) * 16);
}

__device__ __forceinline__ void cp16(uint32_t s, const void* g) {
    asm volatile("cp.async.cg.shared.global [%0], [%1], 16;" :: "r"(s), "l"(g));
}

__device__ __forceinline__ void ldsm4(uint32_t* r, uint32_t addr) {
    asm volatile("ldmatrix.sync.aligned.m8n8.x4.shared.b16 {%0,%1,%2,%3}, [%4];"
                 : "=r"(r[0]), "=r"(r[1]), "=r"(r[2]), "=r"(r[3]) : "r"(addr));
}

__device__ __forceinline__ void mma16816(float* c, const uint32_t* a,
                                         uint32_t b0, uint32_t b1) {
    asm volatile(
        "mma.sync.aligned.m16n8k16.row.col.f32.f16.f16.f32 "
        "{%0,%1,%2,%3}, {%4,%5,%6,%7}, {%8,%9}, {%0,%1,%2,%3};"
        : "+f"(c[0]), "+f"(c[1]), "+f"(c[2]), "+f"(c[3])
        : "r"(a[0]), "r"(a[1]), "r"(a[2]), "r"(a[3]), "r"(b0), "r"(b1));
}

// tanh-form GELU (jax.nn.gelu approximate=True), fp32
__device__ __forceinline__ float gelu_f(float x) {
    float u = 0.7978845608028654f * x * (1.0f + 0.044715f * x * x);
    u = fminf(fmaxf(u, -10.0f), 10.0f);
    float e2 = __expf(2.0f * u);
    float t = __fdividef(e2 - 1.0f, e2 + 1.0f);
    return 0.5f * x * (1.0f + t);
}

// ---------------- GEMM mainloop ---------------------------------------------
// A: [TILE_M, Kh] fp16 K-major, B: [TILE_N, Kh] fp16 K-major (both in gmem).
// acc[mi][ni][4] covers warp tile 64(M) x 32(N).
__device__ __forceinline__ void load_chunk(const __half* A, const __half* B, int Kh,
                                           int kc, uint32_t sbase) {
    const int tid = threadIdx.x;
    const __half* gA = A + (size_t)kc * KC;
    const __half* gB = B + (size_t)kc * KC;
#pragma unroll
    for (int i = 0; i < 4; i++) {             // A: 128 rows x 8 units (1024)
        int u = i * 256 + tid;
        int row = u >> 3, q = u & 7;
        cp16(sw_addr(sbase, row, q), gA + (size_t)row * Kh + q * 8);
    }
#pragma unroll
    for (int i = 0; i < 4; i++) {             // B: 128 rows x 8 units
        int u = i * 256 + tid;
        int row = u >> 3, q = u & 7;
        cp16(sw_addr(sbase + TILE_M * 128, row, q), gB + (size_t)row * Kh + q * 8);
    }
}

__device__ __forceinline__ void gemm_tile(const __half* A, const __half* B, int Kh,
                                          uint32_t smem_base, float acc[4][4][4]) {
    const int tid = threadIdx.x;
    const int l = tid & 31, w = tid >> 5;
    const int wm = w & 1, wn = w >> 1;        // 2(M) x 4(N) warps
    const int nk = Kh / KC;

    load_chunk(A, B, Kh, 0, smem_base);
    asm volatile("cp.async.commit_group;" ::: "memory");
    load_chunk(A, B, Kh, 1, smem_base + STAGE_BYTES);
    asm volatile("cp.async.commit_group;" ::: "memory");

    // per-thread ldmatrix row indices (constant across chunks)
    const int rowA = wm * 64 + ((l >> 3) & 1) * 8 + (l & 7); // + mi*16
    const int rowB = wn * 32 + ((l >> 4) & 1) * 8 + (l & 7); // + n2*16
    const int unitA_l = (l >> 4);          // + ks*2
    const int unitB_l = ((l >> 3) & 1);    // + ks*2

    for (int k = 0; k < nk; ++k) {
        asm volatile("cp.async.wait_group 1;" ::: "memory");
        __syncthreads();
        const uint32_t aB = smem_base + (uint32_t)(k % NSTAGE) * STAGE_BYTES;
        const uint32_t bB = aB + TILE_M * 128;
#pragma unroll
        for (int ks = 0; ks < 4; ++ks) {      // 4 x k16 per 64-chunk
            uint32_t af[4][4], bf[2][4];
#pragma unroll
            for (int mi = 0; mi < 4; ++mi)
                ldsm4(af[mi], sw_addr(aB, rowA + mi * 16, ks * 2 + unitA_l));
#pragma unroll
            for (int n2 = 0; n2 < 2; ++n2)
                ldsm4(bf[n2], sw_addr(bB, rowB + n2 * 16, ks * 2 + unitB_l));
#pragma unroll
            for (int mi = 0; mi < 4; ++mi)
#pragma unroll
                for (int ni = 0; ni < 4; ++ni)
                    mma16816(acc[mi][ni], af[mi],
                             bf[ni >> 1][(ni & 1) * 2], bf[ni >> 1][(ni & 1) * 2 + 1]);
        }
        // No barrier needed here: the load below writes stage (k+2)%3 ==
        // (k-1)%3, and every warp passed this chunk's top barrier only after
        // finishing chunk k-1's ldmatrix reads.
        if (k + 2 < nk)
            load_chunk(A, B, Kh, k + 2, smem_base + (uint32_t)((k + 2) % NSTAGE) * STAGE_BYTES);
        asm volatile("cp.async.commit_group;" ::: "memory");
    }
}

// ---------------- GEMM1: H = gelu(A @ W1^T + b1) ----------------------------
__global__ void __launch_bounds__(256, 2)
gemm1_kernel(const float* __restrict__ b1) {
    extern __shared__ char smem[];
    const int tid = threadIdx.x, l = tid & 31, w = tid >> 5;
    const int wm = w & 1, wn = w >> 1;
    const int nt = blockIdx.x, mt = blockIdx.y, e = blockIdx.z;

    float acc[4][4][4];
#pragma unroll
    for (int i = 0; i < 4; i++)
#pragma unroll
        for (int j = 0; j < 4; j++)
#pragma unroll
            for (int q = 0; q < 4; q++) acc[i][j][q] = 0.f;

    const __half* A = g_Ah  + ((size_t)e * C_DIM + (size_t)mt * TILE_M) * D_DIM;
    const __half* B = g_W1h + (size_t)e * F_DIM * D_DIM + (size_t)nt * TILE_N * D_DIM;
    gemm_tile(A, B, D_DIM, smem_u32(smem), acc);

    const int g = l >> 2, t = l & 3;
    const int col0 = nt * TILE_N + wn * 32;
    const float* bb = b1 + (size_t)e * F_DIM + col0;
#pragma unroll
    for (int mi = 0; mi < 4; ++mi)
#pragma unroll
        for (int h = 0; h < 2; ++h) {
            int row = mt * TILE_M + wm * 64 + mi * 16 + g + h * 8;
            __half2* drow = (__half2*)(g_Hh + ((size_t)e * C_DIM + row) * F_DIM + col0);
#pragma unroll
            for (int ni = 0; ni < 4; ++ni) {
                int c = ni * 8 + 2 * t;
                float v0 = gelu_f(acc[mi][ni][h * 2 + 0] + bb[c]);
                float v1 = gelu_f(acc[mi][ni][h * 2 + 1] + bb[c + 1]);
                drow[c >> 1] = __floats2half2_rn(v0, v1);
            }
        }
}

// ---------------- GEMM2: scatter-add (H @ W2^T + b2) * w --------------------
__global__ void __launch_bounds__(256, 2)
gemm2_kernel(const float* __restrict__ b2, const int* __restrict__ top_idx,
             const float* __restrict__ iw, float* __restrict__ out) {
    extern __shared__ char smem[];
    const int tid = threadIdx.x, l = tid & 31, w = tid >> 5;
    const int wm = w & 1, wn = w >> 1;
    const int nt = blockIdx.x, mt = blockIdx.y, e = blockIdx.z;

    float acc[4][4][4];
#pragma unroll
    for (int i = 0; i < 4; i++)
#pragma unroll
        for (int j = 0; j < 4; j++)
#pragma unroll
            for (int q = 0; q < 4; q++) acc[i][j][q] = 0.f;

    const __half* A = g_Hh  + ((size_t)e * C_DIM + (size_t)mt * TILE_M) * F_DIM;
    const __half* B = g_W2h + (size_t)e * D_DIM * F_DIM + (size_t)nt * TILE_N * F_DIM;
    gemm_tile(A, B, F_DIM, smem_u32(smem), acc);

    const int g = l >> 2, t = l & 3;
    const int col0 = nt * TILE_N + wn * 32;
    const float* bb = b2 + (size_t)e * D_DIM + col0;
#pragma unroll
    for (int mi = 0; mi < 4; ++mi)
#pragma unroll
        for (int h = 0; h < 2; ++h) {
            int row = mt * TILE_M + wm * 64 + mi * 16 + g + h * 8;  // c index
            int tok = top_idx[(size_t)row * E_DIM + e];
            float wgt = iw[(size_t)tok * E_DIM + e];
            float* orow = out + (size_t)tok * D_DIM + col0;
#pragma unroll
            for (int ni = 0; ni < 4; ++ni) {
                int c = ni * 8 + 2 * t;
                atomicAdd(&orow[c],     (acc[mi][ni][h * 2 + 0] + bb[c])     * wgt);
                atomicAdd(&orow[c + 1], (acc[mi][ni][h * 2 + 1] + bb[c + 1]) * wgt);
            }
        }
}

// ---------------- prep kernels ----------------------------------------------
// src [E][R][Cc] fp32 -> dst [E][Cc][R] fp16 (transpose last two dims)
__global__ void transpose_f32_to_f16(const float* __restrict__ src,
                                     __half* __restrict__ dst, int R, int Cc) {
    __shared__ float tile[32][33];
    const int e = blockIdx.z;
    const float* s = src + (size_t)e * R * Cc;
    __half* d = dst + (size_t)e * Cc * R;
    const int r0 = blockIdx.y * 32, c0 = blockIdx.x * 32;
    const int tx = threadIdx.x, ty = threadIdx.y;   // (32, 8)
#pragma unroll
    for (int j = 0; j < 32; j += 8)
        tile[ty + j][tx] = s[(size_t)(r0 + ty + j) * Cc + c0 + tx];
    __syncthreads();
#pragma unroll
    for (int j = 0; j < 32; j += 8)
        d[(size_t)(c0 + ty + j) * R + r0 + tx] = __float2half_rn(tile[tx][ty + j]);
}

__global__ void gather_kernel(const float* __restrict__ inputs,
                              const int* __restrict__ top_idx) {
    const int c = blockIdx.x, e = blockIdx.y;
    const int t = top_idx[(size_t)c * E_DIM + e];
    const float2* src = (const float2*)(inputs + (size_t)t * D_DIM);
    __half2* dst = (__half2*)(g_Ah + ((size_t)e * C_DIM + c) * D_DIM);
    for (int i = threadIdx.x; i < D_DIM / 2; i += blockDim.x) {
        float2 v = src[i];
        dst[i] = __floats2half2_rn(v.x, v.y);
    }
}

// ---------------- launch -----------------------------------------------------
extern "C" void kernel_launch(void* const* d_in, const int* in_sizes, int n_in,
                              void* d_out, int out_size) {
    const float* inputs  = (const float*)d_in[0];
    const float* iw      = (const float*)d_in[1];
    const int*   top_idx = (const int*)d_in[2];
    const float* W1      = (const float*)d_in[3];
    const float* b1      = (const float*)d_in[4];
    const float* W2      = (const float*)d_in[5];
    const float* b2      = (const float*)d_in[6];
    float* out = (float*)d_out;

    cudaFuncSetAttribute(gemm1_kernel,
                         cudaFuncAttributeMaxDynamicSharedMemorySize, SMEM_TOTAL);
    cudaFuncSetAttribute(gemm2_kernel,
                         cudaFuncAttributeMaxDynamicSharedMemorySize, SMEM_TOTAL);

    __half *pW1h, *pW2h;
    cudaGetSymbolAddress((void**)&pW1h, g_W1h);
    cudaGetSymbolAddress((void**)&pW2h, g_W2h);

    cudaMemsetAsync(d_out, 0, (size_t)T_DIM * D_DIM * sizeof(float), 0);

    dim3 tb(32, 8);
    transpose_f32_to_f16<<<dim3(F_DIM / 32, D_DIM / 32, E_DIM), tb>>>(W1, pW1h, D_DIM, F_DIM);
    transpose_f32_to_f16<<<dim3(D_DIM / 32, F_DIM / 32, E_DIM), tb>>>(W2, pW2h, F_DIM, D_DIM);
    gather_kernel<<<dim3(C_DIM, E_DIM), 256>>>(inputs, top_idx);

    gemm1_kernel<<<dim3(F_DIM / TILE_N, C_DIM / TILE_M, E_DIM), 256, SMEM_TOTAL>>>(b1);
    gemm2_kernel<<<dim3(D_DIM / TILE_N, C_DIM / TILE_M, E_DIM), 256, SMEM_TOTAL>>>(
        b2, top_idx, iw, out);
}